// round 3
// baseline (speedup 1.0000x reference)
#include <cuda_runtime.h>
#include <cuda_bf16.h>
#include <math.h>

#define NB     32
#define NEV    393216
#define NSEG   48
#define SEGLEN 8192
#define WID    320
#define HEI    240
#define HW     76800
#define NWORD  2400        // HW/32
#define SIDX_C 4
#define EIDX_C 38
#define ROWS_USED 34       // rows 4..37 (row index 0..33)
#define NSTEP  33

// ---------------- device scratch ----------------
__device__ int           g_mom[NB * NSEG * 10];
__device__ unsigned      g_packed[(size_t)NB * ROWS_USED * SEGLEN]; // (y<<9)|x
__device__ int           g_aligned[NB * NSEG * 2];
__device__ unsigned char g_flags[NB * NSTEP];
__device__ unsigned      g_raw[(size_t)NB * ROWS_USED * NWORD];     // per-row bitmaps
__device__ unsigned char g_applied[NB * ROWS_USED];
__device__ int           g_cont[(size_t)NB * HW];

// ---------------- K1: histogram moments + packed coords + zero scratch ----------------
__global__ void __launch_bounds__(256) k_hist(const int* __restrict__ ev) {
    __shared__ int shx[WID];
    __shared__ int shy[HEI];
    __shared__ int sm1x, sm1y;
    int bx = blockIdx.x;
    int b = bx / NSEG, s = bx % NSEG;
    int t = threadIdx.x;
    int gt = bx * 256 + t;

    // zero g_raw + g_cont (grid-strided, vectorized)
    {
        uint4 z = make_uint4(0u, 0u, 0u, 0u);
        uint4* zr = (uint4*)g_raw;
        const int NR4 = NB * ROWS_USED * NWORD / 4;       // 652800
        for (int i = gt; i < NR4; i += NB * NSEG * 256) zr[i] = z;
        uint4* zc = (uint4*)g_cont;
        const int NC4 = NB * HW / 4;                       // 614400
        for (int i = gt; i < NC4; i += NB * NSEG * 256) zc[i] = z;
    }

    for (int e = t; e < WID; e += 256) shx[e] = 0;
    for (int e = t; e < HEI; e += 256) shy[e] = 0;
    if (t == 0) { sm1x = 0; sm1y = 0; }
    __syncthreads();

    const uint4* evv = (const uint4*)(ev + ((size_t)b * NEV + (size_t)s * SEGLEN) * 5);
    bool wr = (s >= SIDX_C && s < EIDX_C);
    int sp = s - SIDX_C; if (sp < 0) sp = 0;
    uint4* pk4 = (uint4*)(g_packed + ((size_t)b * ROWS_USED + sp) * SEGLEN);

    for (int g = t; g < SEGLEN / 4; g += 256) {
        uint4 a0 = evv[g * 5 + 0];
        uint4 a1 = evv[g * 5 + 1];
        uint4 a2 = evv[g * 5 + 2];
        uint4 a3 = evv[g * 5 + 3];
        uint4 a4 = evv[g * 5 + 4];
        int x0 = (int)a0.x, y0 = (int)a0.y;
        int x1 = (int)a1.y, y1 = (int)a1.z;
        int x2 = (int)a2.z, y2 = (int)a2.w;
        int x3 = (int)a3.w, y3 = (int)a4.x;
        atomicAdd(&shx[x0], 1); atomicAdd(&shy[y0], 1);
        atomicAdd(&shx[x1], 1); atomicAdd(&shy[y1], 1);
        atomicAdd(&shx[x2], 1); atomicAdd(&shy[y2], 1);
        atomicAdd(&shx[x3], 1); atomicAdd(&shy[y3], 1);
        if (wr) {
            uint4 p;
            p.x = (unsigned)((y0 << 9) | x0);
            p.y = (unsigned)((y1 << 9) | x1);
            p.z = (unsigned)((y2 << 9) | x2);
            p.w = (unsigned)((y3 << 9) | x3);
            pk4[g] = p;
        }
    }
    __syncthreads();

    int l1 = 0, l2 = 0;
    for (int e = t; e < WID; e += 256) l1 += e * shx[e];
    for (int e = t; e < HEI; e += 256) l2 += e * shy[e];
    for (int o = 16; o; o >>= 1) {
        l1 += __shfl_down_sync(0xffffffffu, l1, o);
        l2 += __shfl_down_sync(0xffffffffu, l2, o);
    }
    if ((t & 31) == 0) { atomicAdd(&sm1x, l1); atomicAdd(&sm1y, l2); }
    __syncthreads();

    if (t == 0) {
        int* mm = g_mom + (b * NSEG + s) * 10;
        mm[0] = sm1x; mm[1] = shx[0]; mm[2] = shx[1]; mm[3] = shx[WID - 2]; mm[4] = shx[WID - 1];
        mm[5] = sm1y; mm[6] = shy[0]; mm[7] = shy[1]; mm[8] = shy[HEI - 2]; mm[9] = shy[HEI - 1];
    }
}

// ---------------- K2: means + aligned + outlier flags ----------------
__device__ __forceinline__ void sort10(float* a) {
    #pragma unroll
    for (int i = 1; i < 10; i++) {
        float v = a[i]; int j = i - 1;
        while (j >= 0 && a[j] > v) { a[j + 1] = a[j]; j--; }
        a[j + 1] = v;
    }
}

__device__ bool outl(const float* m, int i) {
    float w[10], s[10];
    #pragma unroll
    for (int t = 0; t < 10; t++) { w[t] = m[i + t]; s[t] = w[t]; }
    sort10(s);
    float med = 0.5f * (s[4] + s[5]);
    float d0 = fabsf(w[0] - med);
    float ds[10];
    #pragma unroll
    for (int t = 0; t < 10; t++) ds[t] = fabsf(w[t] - med);
    sort10(ds);
    float mad = 0.5f * (ds[4] + ds[5]);
    float mz = (0.6745f * d0) / mad;
    return mz > 3.0f;
}

__global__ void __launch_bounds__(128) k_mean(const float* __restrict__ kern) {
    __shared__ float skk[25];
    __shared__ float smX[NSEG], smY[NSEG];
    int b = blockIdx.x, t = threadIdx.x;
    if (t < 25) skk[t] = kern[t];
    __syncthreads();

    if (t < 96) {
        int coord = t / NSEG, s = t % NSEG;
        int D = coord ? HEI : WID;
        double num = 0.0;
        #pragma unroll
        for (int a = -2; a <= 2; a++) {
            int si = s + a;
            if (si < 0 || si >= NSEG) continue;
            const int* mm = g_mom + (b * NSEG + si) * 10 + coord * 5;
            double m1  = (double)mm[0];
            double h0  = (double)mm[1];
            double h1  = (double)mm[2];
            double hD2 = (double)mm[3];
            double hD1 = (double)mm[4];
            double kr0 = skk[(a + 2) * 5 + 0];
            double kr1 = skk[(a + 2) * 5 + 1];
            double kr2 = skk[(a + 2) * 5 + 2];
            double kr3 = skk[(a + 2) * 5 + 3];
            double kr4 = skk[(a + 2) * 5 + 4];
            double Ka = kr0 + kr1 + kr2 + kr3 + kr4;
            double Sb = -2.0 * kr0 - kr1 + kr3 + 2.0 * kr4;
            num += Ka * m1 - Sb * (double)SEGLEN
                 + h0 * (kr3 + 2.0 * kr4) + h1 * kr4
                 - hD1 * ((double)D * kr1 + (double)(D + 1) * kr0)
                 - hD2 * ((double)D * kr0);
        }
        float mean = (float)(num / (double)SEGLEN);
        if (coord) smY[s] = mean; else smX[s] = mean;
    }
    __syncthreads();

    if (t < 96) {
        int coord = t / NSEG, s = t % NSEG;
        int D = coord ? HEI : WID;
        const float* m = coord ? smY : smX;
        float start = m[SIDX_C];
        float dis = (float)(D / 2) - start;
        float a = rintf((m[s] - start) - dis);
        g_aligned[(b * NSEG + s) * 2 + coord] = (int)a;
    }
    if (t < NSTEP) {
        bool fx = outl(smX, SIDX_C + 1 + t);
        bool fy = outl(smY, SIDX_C + 1 + t);
        g_flags[b * NSTEP + t] = (fx || fy) ? 1 : 0;
    }
}

// ---------------- K3: per-row bitmaps via direct global RED.OR ----------------
__global__ void __launch_bounds__(256) k_rowbits() {
    int b = blockIdx.x / ROWS_USED, row = blockIdx.x % ROWS_USED;
    if (row > 0 && g_flags[b * NSTEP + row - 1]) return;   // outlier: row never used
    int t = threadIdx.x;

    const uint4* pk4 = (const uint4*)(g_packed + ((size_t)b * ROWS_USED + row) * SEGLEN);
    int s = row + SIDX_C;
    int ax = g_aligned[(b * NSEG + s) * 2];
    int ay = g_aligned[(b * NSEG + s) * 2 + 1];
    unsigned* dst = g_raw + (size_t)(b * ROWS_USED + row) * NWORD;

    for (int g = t; g < SEGLEN / 4; g += 256) {
        uint4 v = pk4[g];
        unsigned vs[4] = {v.x, v.y, v.z, v.w};
        #pragma unroll
        for (int k = 0; k < 4; k++) {
            int x = (int)(vs[k] & 511u), y = (int)(vs[k] >> 9);
            int xx = min(max(x - ax, 0), WID - 1);
            int yy = min(max(y - ay, 0), HEI - 1);
            int p = yy * WID + xx;
            atomicOr(&dst[p >> 5], 1u << (p & 31));        // RED.OR (no return)
        }
    }
}

// ---------------- K4: parallel prefix-union scan + conf + conf-normalize ----------------
// term_k = raw_k & prefix_{k-1} & prefix_{k-2}; stop from prefix popcounts. 2 barriers total.
__global__ void __launch_bounds__(800, 1) k_scan2(float* __restrict__ out) {
    __shared__ unsigned char s_act[ROWS_USED];
    __shared__ int s_nact;
    __shared__ int s_cnt[ROWS_USED];
    __shared__ double s_sum, s_sq;

    int b = blockIdx.x, t = threadIdx.x;
    const unsigned* rawb = g_raw + (size_t)b * ROWS_USED * NWORD;
    int wi0 = t, wi1 = t + 800, wi2 = t + 1600;

    if (t == 0) {
        int n = 0;
        s_act[n++] = 0;
        for (int r = 1; r < ROWS_USED; r++)
            if (!g_flags[b * NSTEP + r - 1]) s_act[n++] = (unsigned char)r;
        s_nact = n;
        s_sum = 0.0; s_sq = 0.0;
    }
    if (t < ROWS_USED) { s_cnt[t] = 0; g_applied[b * ROWS_USED + t] = 0; }
    __syncthreads();

    int nact = s_nact;

    // ---- pass 1: prefix-union popcounts ----
    unsigned u0 = 0u, u1 = 0u, u2 = 0u;
    for (int i = 0; i < nact; i++) {
        const unsigned* rp = rawb + (size_t)s_act[i] * NWORD;
        u0 |= rp[wi0]; u1 |= rp[wi1]; u2 |= rp[wi2];
        int c = __popc(u0) + __popc(u1) + __popc(u2);
        c = __reduce_add_sync(0xffffffffu, (unsigned)c);
        if ((t & 31) == 0) atomicAdd(&s_cnt[i], c);
    }
    __syncthreads();

    // ---- stop decision (every thread, identical) ----
    int kstop = nact;                      // nact => never stopped
    for (int i = 1; i < nact; i++) {
        int newc = s_cnt[i] - s_cnt[i - 1];
        float ratio = (float)newc / (float)s_cnt[i];
        if (ratio < 0.01f) { kstop = i; break; }
    }
    int kend = kstop < nact - 1 ? kstop : nact - 1;   // last conf step
    int kapplied = (kstop == nact) ? nact - 1 : kstop - 1;
    if (t < nact) g_applied[b * ROWS_USED + s_act[t]] = (t <= kapplied) ? 1 : 0;

    // ---- pass 2: conf bitplanes in registers (no barriers) ----
    unsigned A0, A1, A2, B0 = 0xffffffffu, B1 = 0xffffffffu, B2 = 0xffffffffu;
    {
        const unsigned* rp = rawb;         // active row 0 == row 0
        A0 = rp[wi0]; A1 = rp[wi1]; A2 = rp[wi2];
    }
    unsigned c0[3] = {0,0,0}, c1[3] = {0,0,0}, c2[3] = {0,0,0},
             c3[3] = {0,0,0}, c4[3] = {0,0,0}, c5[3] = {0,0,0};
    for (int k = 1; k <= kend; k++) {
        const unsigned* rp = rawb + (size_t)s_act[k] * NWORD;
        unsigned w0 = rp[wi0], w1 = rp[wi1], w2 = rp[wi2];
        unsigned tm[3] = { w0 & A0 & B0, w1 & A1 & B1, w2 & A2 & B2 };
        #pragma unroll
        for (int j = 0; j < 3; j++) {
            unsigned carry = tm[j], nx;
            nx = c0[j] & carry; c0[j] ^= carry; carry = nx;
            nx = c1[j] & carry; c1[j] ^= carry; carry = nx;
            nx = c2[j] & carry; c2[j] ^= carry; carry = nx;
            nx = c3[j] & carry; c3[j] ^= carry; carry = nx;
            nx = c4[j] & carry; c4[j] ^= carry; carry = nx;
            c5[j] ^= carry;
        }
        B0 = A0; B1 = A1; B2 = A2;
        A0 |= w0; A1 |= w1; A2 |= w2;
    }

    // ---- assemble conf values, accumulate sum/sumsq ----
    int vals[3][32];
    double ls = 0.0, lq = 0.0;
    #pragma unroll
    for (int j = 0; j < 3; j++) {
        #pragma unroll
        for (int bit = 0; bit < 32; bit++) {
            int v =  (int)((c0[j] >> bit) & 1u)
                  | ((int)((c1[j] >> bit) & 1u) << 1)
                  | ((int)((c2[j] >> bit) & 1u) << 2)
                  | ((int)((c3[j] >> bit) & 1u) << 3)
                  | ((int)((c4[j] >> bit) & 1u) << 4)
                  | ((int)((c5[j] >> bit) & 1u) << 5);
            vals[j][bit] = v;
            double dv = (double)v;
            ls += dv; lq += dv * dv;
        }
    }
    for (int o = 16; o; o >>= 1) {
        ls += __shfl_down_sync(0xffffffffu, ls, o);
        lq += __shfl_down_sync(0xffffffffu, lq, o);
    }
    if ((t & 31) == 0) { atomicAdd(&s_sum, ls); atomicAdd(&s_sq, lq); }
    __syncthreads();

    double n = (double)HW;
    double mu = s_sum / n;
    double var = (s_sq - s_sum * s_sum / n) / (n - 1.0);
    if (var < 0.0) var = 0.0;
    float clampv = (float)(mu + 3.0 * sqrt(var));

    // write normalized conf directly to output channel 1
    float* op = out + ((size_t)b * 2 + 1) * HW;
    int wis[3] = { wi0, wi1, wi2 };
    #pragma unroll
    for (int j = 0; j < 3; j++) {
        float4* d4 = (float4*)(op + wis[j] * 32);
        #pragma unroll
        for (int q = 0; q < 8; q++) {
            float4 f;
            f.x = fminf((float)vals[j][q * 4 + 0], clampv) / clampv;
            f.y = fminf((float)vals[j][q * 4 + 1], clampv) / clampv;
            f.z = fminf((float)vals[j][q * 4 + 2], clampv) / clampv;
            f.w = fminf((float)vals[j][q * 4 + 3], clampv) / clampv;
            d4[q] = f;
        }
    }
}

// ---------------- K5: container histogram for applied rows ----------------
__global__ void __launch_bounds__(256) k_cont() {
    int b = blockIdx.x / ROWS_USED, row = blockIdx.x % ROWS_USED;
    if (!g_applied[b * ROWS_USED + row]) return;
    int t = threadIdx.x;

    const uint4* pk4 = (const uint4*)(g_packed + ((size_t)b * ROWS_USED + row) * SEGLEN);
    int s = row + SIDX_C;
    int ax = g_aligned[(b * NSEG + s) * 2];
    int ay = g_aligned[(b * NSEG + s) * 2 + 1];
    int* cont = g_cont + (size_t)b * HW;

    for (int g = t; g < SEGLEN / 4; g += 256) {
        uint4 v = pk4[g];
        unsigned vs[4] = {v.x, v.y, v.z, v.w};
        #pragma unroll
        for (int k = 0; k < 4; k++) {
            int x = (int)(vs[k] & 511u), y = (int)(vs[k] >> 9);
            int xx = min(max(x - ax, 0), WID - 1);
            int yy = min(max(y - ay, 0), HEI - 1);
            atomicAdd(&cont[yy * WID + xx], 1);
        }
    }
}

// ---------------- K6: normalize container only ----------------
__global__ void __launch_bounds__(1024) k_norm(float* __restrict__ out) {
    __shared__ double s_sum, s_sq;
    int b = blockIdx.x;
    int t = threadIdx.x;
    const int* src = g_cont + (size_t)b * HW;

    if (t == 0) { s_sum = 0.0; s_sq = 0.0; }
    __syncthreads();
    double ls = 0.0, lq = 0.0;
    for (int p = t; p < HW; p += 1024) {
        double v = (double)src[p];
        ls += v; lq += v * v;
    }
    for (int o = 16; o; o >>= 1) {
        ls += __shfl_down_sync(0xffffffffu, ls, o);
        lq += __shfl_down_sync(0xffffffffu, lq, o);
    }
    if ((t & 31) == 0) { atomicAdd(&s_sum, ls); atomicAdd(&s_sq, lq); }
    __syncthreads();
    double n = (double)HW;
    double mu = s_sum / n;
    double var = (s_sq - s_sum * s_sum / n) / (n - 1.0);
    if (var < 0.0) var = 0.0;
    float clampv = (float)(mu + 3.0 * sqrt(var));
    float* op = out + (size_t)b * 2 * HW;
    for (int p = t; p < HW; p += 1024) {
        float v = (float)src[p];
        op[p] = fminf(v, clampv) / clampv;
    }
}

// ---------------- launch ----------------
extern "C" void kernel_launch(void* const* d_in, const int* in_sizes, int n_in,
                              void* d_out, int out_size) {
    const int*   ev   = (const int*)d_in[0];
    const float* kern = (const float*)d_in[1];
    float*       out  = (float*)d_out;
    (void)in_sizes; (void)n_in; (void)out_size;

    k_hist<<<NB * NSEG, 256>>>(ev);
    k_mean<<<NB, 128>>>(kern);
    k_rowbits<<<NB * ROWS_USED, 256>>>();
    k_scan2<<<NB, 800>>>(out);
    k_cont<<<NB * ROWS_USED, 256>>>();
    k_norm<<<NB, 1024>>>(out);
}

// round 4
// speedup vs baseline: 1.6284x; 1.6284x over previous
#include <cuda_runtime.h>
#include <cuda_bf16.h>
#include <math.h>

#define NB     32
#define NEV    393216
#define NSEG   48
#define SEGLEN 8192
#define WID    320
#define HEI    240
#define HW     76800
#define NWORD  2400        // HW/32
#define SIDX_C 4
#define EIDX_C 38
#define ROWS_USED 34       // rows 4..37 (row index 0..33)
#define NSTEP  33
#define WBLK   10          // word-blocks per batch (10*256 >= 2400)

// ---------------- device scratch ----------------
__device__ int                g_mom[NB * NSEG * 10];
__device__ unsigned           g_packed[(size_t)NB * ROWS_USED * SEGLEN]; // (y<<9)|x
__device__ int                g_aligned[NB * NSEG * 2];
__device__ unsigned long long g_actmask[NB];
__device__ unsigned long long g_contrib[NB];
__device__ int                g_cnt[NB * ROWS_USED];
__device__ int                g_stat[NB * 2];                 // conf sum, sumsq (int exact)
__device__ unsigned           g_raw[(size_t)NB * ROWS_USED * NWORD];
__device__ unsigned char      g_applied[NB * ROWS_USED];
__device__ unsigned char      g_conf8[(size_t)NB * HW];
__device__ int                g_cont[(size_t)NB * HW];

// ---------------- K1: histogram moments + packed coords + zero cont ----------------
__global__ void __launch_bounds__(256) k_hist(const int* __restrict__ ev) {
    __shared__ int shx[WID];
    __shared__ int shy[HEI];
    __shared__ int sm1x, sm1y;
    int bx = blockIdx.x;
    int b = bx / NSEG, s = bx % NSEG;
    int t = threadIdx.x;
    int gt = bx * 256 + t;

    // zero g_cont (grid-strided uint4)
    {
        uint4 z = make_uint4(0u, 0u, 0u, 0u);
        uint4* zc = (uint4*)g_cont;
        const int NC4 = NB * HW / 4;
        for (int i = gt; i < NC4; i += NB * NSEG * 256) zc[i] = z;
    }

    for (int e = t; e < WID; e += 256) shx[e] = 0;
    for (int e = t; e < HEI; e += 256) shy[e] = 0;
    if (t == 0) { sm1x = 0; sm1y = 0; }
    __syncthreads();

    const uint4* evv = (const uint4*)(ev + ((size_t)b * NEV + (size_t)s * SEGLEN) * 5);
    bool wr = (s >= SIDX_C && s < EIDX_C);
    int sp = s - SIDX_C; if (sp < 0) sp = 0;
    uint4* pk4 = (uint4*)(g_packed + ((size_t)b * ROWS_USED + sp) * SEGLEN);

    for (int g = t; g < SEGLEN / 4; g += 256) {
        uint4 a0 = evv[g * 5 + 0];
        uint4 a1 = evv[g * 5 + 1];
        uint4 a2 = evv[g * 5 + 2];
        uint4 a3 = evv[g * 5 + 3];
        uint4 a4 = evv[g * 5 + 4];
        int x0 = (int)a0.x, y0 = (int)a0.y;
        int x1 = (int)a1.y, y1 = (int)a1.z;
        int x2 = (int)a2.z, y2 = (int)a2.w;
        int x3 = (int)a3.w, y3 = (int)a4.x;
        atomicAdd(&shx[x0], 1); atomicAdd(&shy[y0], 1);
        atomicAdd(&shx[x1], 1); atomicAdd(&shy[y1], 1);
        atomicAdd(&shx[x2], 1); atomicAdd(&shy[y2], 1);
        atomicAdd(&shx[x3], 1); atomicAdd(&shy[y3], 1);
        if (wr) {
            uint4 p;
            p.x = (unsigned)((y0 << 9) | x0);
            p.y = (unsigned)((y1 << 9) | x1);
            p.z = (unsigned)((y2 << 9) | x2);
            p.w = (unsigned)((y3 << 9) | x3);
            pk4[g] = p;
        }
    }
    __syncthreads();

    int l1 = 0, l2 = 0;
    for (int e = t; e < WID; e += 256) l1 += e * shx[e];
    for (int e = t; e < HEI; e += 256) l2 += e * shy[e];
    for (int o = 16; o; o >>= 1) {
        l1 += __shfl_down_sync(0xffffffffu, l1, o);
        l2 += __shfl_down_sync(0xffffffffu, l2, o);
    }
    if ((t & 31) == 0) { atomicAdd(&sm1x, l1); atomicAdd(&sm1y, l2); }
    __syncthreads();

    if (t == 0) {
        int* mm = g_mom + (b * NSEG + s) * 10;
        mm[0] = sm1x; mm[1] = shx[0]; mm[2] = shx[1]; mm[3] = shx[WID - 2]; mm[4] = shx[WID - 1];
        mm[5] = sm1y; mm[6] = shy[0]; mm[7] = shy[1]; mm[8] = shy[HEI - 2]; mm[9] = shy[HEI - 1];
    }
}

// ---------------- K2: means + aligned + outlier flags -> active mask; zero small scratch ----------------
__device__ __forceinline__ void sort10(float* a) {
    #pragma unroll
    for (int i = 1; i < 10; i++) {
        float v = a[i]; int j = i - 1;
        while (j >= 0 && a[j] > v) { a[j + 1] = a[j]; j--; }
        a[j + 1] = v;
    }
}

__device__ bool outl(const float* m, int i) {
    float w[10], s[10];
    #pragma unroll
    for (int t = 0; t < 10; t++) { w[t] = m[i + t]; s[t] = w[t]; }
    sort10(s);
    float med = 0.5f * (s[4] + s[5]);
    float d0 = fabsf(w[0] - med);
    float ds[10];
    #pragma unroll
    for (int t = 0; t < 10; t++) ds[t] = fabsf(w[t] - med);
    sort10(ds);
    float mad = 0.5f * (ds[4] + ds[5]);
    float mz = (0.6745f * d0) / mad;
    return mz > 3.0f;
}

__global__ void __launch_bounds__(128) k_mean(const float* __restrict__ kern) {
    __shared__ float skk[25];
    __shared__ float smX[NSEG], smY[NSEG];
    __shared__ unsigned char s_flag[NSTEP];
    int b = blockIdx.x, t = threadIdx.x;
    if (t < 25) skk[t] = kern[t];
    if (t < ROWS_USED) g_cnt[b * ROWS_USED + t] = 0;
    if (t == 0) { g_stat[b * 2] = 0; g_stat[b * 2 + 1] = 0; }
    __syncthreads();

    if (t < 96) {
        int coord = t / NSEG, s = t % NSEG;
        int D = coord ? HEI : WID;
        double num = 0.0;
        #pragma unroll
        for (int a = -2; a <= 2; a++) {
            int si = s + a;
            if (si < 0 || si >= NSEG) continue;
            const int* mm = g_mom + (b * NSEG + si) * 10 + coord * 5;
            double m1  = (double)mm[0];
            double h0  = (double)mm[1];
            double h1  = (double)mm[2];
            double hD2 = (double)mm[3];
            double hD1 = (double)mm[4];
            double kr0 = skk[(a + 2) * 5 + 0];
            double kr1 = skk[(a + 2) * 5 + 1];
            double kr2 = skk[(a + 2) * 5 + 2];
            double kr3 = skk[(a + 2) * 5 + 3];
            double kr4 = skk[(a + 2) * 5 + 4];
            double Ka = kr0 + kr1 + kr2 + kr3 + kr4;
            double Sb = -2.0 * kr0 - kr1 + kr3 + 2.0 * kr4;
            num += Ka * m1 - Sb * (double)SEGLEN
                 + h0 * (kr3 + 2.0 * kr4) + h1 * kr4
                 - hD1 * ((double)D * kr1 + (double)(D + 1) * kr0)
                 - hD2 * ((double)D * kr0);
        }
        float mean = (float)(num / (double)SEGLEN);
        if (coord) smY[s] = mean; else smX[s] = mean;
    }
    __syncthreads();

    if (t < 96) {
        int coord = t / NSEG, s = t % NSEG;
        int D = coord ? HEI : WID;
        const float* m = coord ? smY : smX;
        float start = m[SIDX_C];
        float dis = (float)(D / 2) - start;
        float a = rintf((m[s] - start) - dis);
        g_aligned[(b * NSEG + s) * 2 + coord] = (int)a;
    }
    if (t < NSTEP) {
        bool fx = outl(smX, SIDX_C + 1 + t);
        bool fy = outl(smY, SIDX_C + 1 + t);
        s_flag[t] = (fx || fy) ? 1 : 0;
    }
    __syncthreads();
    if (t == 0) {
        unsigned long long m = 1ull;                 // row 0 always active
        for (int r = 1; r < ROWS_USED; r++)
            if (!s_flag[r - 1]) m |= 1ull << r;
        g_actmask[b] = m;
    }
}

// ---------------- K3: per-row bitmaps (shared staging, R2-proven) ----------------
__global__ void __launch_bounds__(256) k_rowbits() {
    __shared__ unsigned bits[NWORD];
    int b = blockIdx.x / ROWS_USED, row = blockIdx.x % ROWS_USED;
    int t = threadIdx.x;

    for (int w = t; w < NWORD; w += 256) bits[w] = 0u;
    __syncthreads();

    const uint4* pk4 = (const uint4*)(g_packed + ((size_t)b * ROWS_USED + row) * SEGLEN);
    int s = row + SIDX_C;
    int ax = g_aligned[(b * NSEG + s) * 2];
    int ay = g_aligned[(b * NSEG + s) * 2 + 1];

    for (int g = t; g < SEGLEN / 4; g += 256) {
        uint4 v = pk4[g];
        unsigned vs[4] = {v.x, v.y, v.z, v.w};
        #pragma unroll
        for (int k = 0; k < 4; k++) {
            int x = (int)(vs[k] & 511u), y = (int)(vs[k] >> 9);
            int xx = min(max(x - ax, 0), WID - 1);
            int yy = min(max(y - ay, 0), HEI - 1);
            int p = yy * WID + xx;
            atomicOr(&bits[p >> 5], 1u << (p & 31));
        }
    }
    __syncthreads();

    unsigned* dst = g_raw + (size_t)(b * ROWS_USED + row) * NWORD;
    for (int w = t; w < NWORD; w += 256) dst[w] = bits[w];
}

// ---------------- K4a: word-parallel prefix-union popcounts (fully unrolled) ----------------
__global__ void __launch_bounds__(256) k_pref() {
    __shared__ int s_cnt[ROWS_USED];
    int b = blockIdx.x / WBLK, wb = blockIdx.x % WBLK;
    int t = threadIdx.x;
    int w = wb * 256 + t;
    bool val = (w < NWORD);
    const unsigned* rawb = g_raw + (size_t)b * ROWS_USED * NWORD + (val ? w : 0);
    unsigned long long mask = g_actmask[b];

    unsigned wv[ROWS_USED];
    #pragma unroll
    for (int r = 0; r < ROWS_USED; r++) wv[r] = val ? rawb[(size_t)r * NWORD] : 0u;

    if (t < ROWS_USED) s_cnt[t] = 0;
    __syncthreads();

    unsigned u = 0u;
    #pragma unroll
    for (int r = 0; r < ROWS_USED; r++) {
        if ((mask >> r) & 1ull) u |= wv[r];
        unsigned c = __reduce_add_sync(0xffffffffu, (unsigned)__popc(u));
        if ((t & 31) == 0) atomicAdd(&s_cnt[r], (int)c);
    }
    __syncthreads();
    if (t < ROWS_USED) atomicAdd(&g_cnt[b * ROWS_USED + t], s_cnt[t]);
}

// ---------------- K4b: stop decision per batch ----------------
__global__ void __launch_bounds__(64) k_decide() {
    __shared__ int s_c[ROWS_USED];
    int b = blockIdx.x, t = threadIdx.x;
    if (t < ROWS_USED) s_c[t] = g_cnt[b * ROWS_USED + t];
    __syncthreads();
    if (t == 0) {
        unsigned long long mask = g_actmask[b];
        unsigned long long contrib = 0ull;
        unsigned char app[ROWS_USED];
        app[0] = 1;
        int prev = s_c[0];
        bool stopped = false;
        for (int r = 1; r < ROWS_USED; r++) {
            app[r] = 0;
            if (!((mask >> r) & 1ull) || stopped) continue;
            int cur = s_c[r];
            int newc = cur - prev;
            float ratio = (float)newc / (float)cur;
            contrib |= 1ull << r;                     // conf updates at this step
            if (ratio < 0.01f) { stopped = true; }
            else { app[r] = 1; prev = cur; }
        }
        g_contrib[b] = contrib;
        for (int r = 0; r < ROWS_USED; r++) g_applied[b * ROWS_USED + r] = app[r];
    }
}

// ---------------- K4c: word-parallel conf bitplanes + int-exact stats ----------------
__global__ void __launch_bounds__(256) k_conf() {
    __shared__ int s_ls, s_lq;
    int b = blockIdx.x / WBLK, wb = blockIdx.x % WBLK;
    int t = threadIdx.x;
    int w = wb * 256 + t;
    bool val = (w < NWORD);
    const unsigned* rawb = g_raw + (size_t)b * ROWS_USED * NWORD + (val ? w : 0);
    unsigned long long contrib = g_contrib[b];

    unsigned wv[ROWS_USED];
    #pragma unroll
    for (int r = 0; r < ROWS_USED; r++) wv[r] = val ? rawb[(size_t)r * NWORD] : 0u;

    if (t == 0) { s_ls = 0; s_lq = 0; }
    __syncthreads();

    unsigned A = wv[0], B = 0xffffffffu;
    unsigned p0 = 0, p1 = 0, p2 = 0, p3 = 0, p4 = 0, p5 = 0;
    #pragma unroll
    for (int r = 1; r < ROWS_USED; r++) {
        if ((contrib >> r) & 1ull) {
            unsigned carry = wv[r] & A & B, nx;
            nx = p0 & carry; p0 ^= carry; carry = nx;
            nx = p1 & carry; p1 ^= carry; carry = nx;
            nx = p2 & carry; p2 ^= carry; carry = nx;
            nx = p3 & carry; p3 ^= carry; carry = nx;
            nx = p4 & carry; p4 ^= carry; carry = nx;
            p5 ^= carry;
            B = A; A |= wv[r];
        }
    }

    int ls = 0, lq = 0;
    unsigned vb[8];                                    // 32 bytes packed
    #pragma unroll
    for (int q = 0; q < 8; q++) {
        unsigned pk = 0;
        #pragma unroll
        for (int k = 0; k < 4; k++) {
            int bit = q * 4 + k;
            int v =  (int)((p0 >> bit) & 1u)
                  | ((int)((p1 >> bit) & 1u) << 1)
                  | ((int)((p2 >> bit) & 1u) << 2)
                  | ((int)((p3 >> bit) & 1u) << 3)
                  | ((int)((p4 >> bit) & 1u) << 4)
                  | ((int)((p5 >> bit) & 1u) << 5);
            pk |= (unsigned)v << (k * 8);
            ls += v; lq += v * v;
        }
        vb[q] = pk;
    }
    if (val) {
        uint4* dst = (uint4*)(g_conf8 + (size_t)b * HW + (size_t)w * 32);
        dst[0] = make_uint4(vb[0], vb[1], vb[2], vb[3]);
        dst[1] = make_uint4(vb[4], vb[5], vb[6], vb[7]);
    }
    for (int o = 16; o; o >>= 1) {
        ls += __shfl_down_sync(0xffffffffu, ls, o);
        lq += __shfl_down_sync(0xffffffffu, lq, o);
    }
    if ((t & 31) == 0) { atomicAdd(&s_ls, ls); atomicAdd(&s_lq, lq); }
    __syncthreads();
    if (t == 0) { atomicAdd(&g_stat[b * 2], s_ls); atomicAdd(&g_stat[b * 2 + 1], s_lq); }
}

// ---------------- K5: container histogram for applied rows ----------------
__global__ void __launch_bounds__(256) k_cont() {
    int b = blockIdx.x / ROWS_USED, row = blockIdx.x % ROWS_USED;
    if (!g_applied[b * ROWS_USED + row]) return;
    int t = threadIdx.x;

    const uint4* pk4 = (const uint4*)(g_packed + ((size_t)b * ROWS_USED + row) * SEGLEN);
    int s = row + SIDX_C;
    int ax = g_aligned[(b * NSEG + s) * 2];
    int ay = g_aligned[(b * NSEG + s) * 2 + 1];
    int* cont = g_cont + (size_t)b * HW;

    for (int g = t; g < SEGLEN / 4; g += 256) {
        uint4 v = pk4[g];
        unsigned vs[4] = {v.x, v.y, v.z, v.w};
        #pragma unroll
        for (int k = 0; k < 4; k++) {
            int x = (int)(vs[k] & 511u), y = (int)(vs[k] >> 9);
            int xx = min(max(x - ax, 0), WID - 1);
            int yy = min(max(y - ay, 0), HEI - 1);
            atomicAdd(&cont[yy * WID + xx], 1);
        }
    }
}

// ---------------- K6: normalize both channels ----------------
__global__ void __launch_bounds__(512) k_norm(float* __restrict__ out) {
    __shared__ double s_sum, s_sq;
    int b = blockIdx.x >> 1, pass = blockIdx.x & 1;
    int t = threadIdx.x;
    double n = (double)HW;

    if (pass == 1) {
        // conf channel: stats precomputed (integer exact)
        double sum = (double)g_stat[b * 2];
        double sq  = (double)g_stat[b * 2 + 1];
        double mu = sum / n;
        double var = (sq - sum * sum / n) / (n - 1.0);
        if (var < 0.0) var = 0.0;
        float clampv = (float)(mu + 3.0 * sqrt(var));
        const unsigned char* src = g_conf8 + (size_t)b * HW;
        float* op = out + ((size_t)b * 2 + 1) * HW;
        const uint4* s4 = (const uint4*)src;
        for (int q = t; q < HW / 16; q += 512) {
            uint4 pk = s4[q];
            unsigned ws[4] = { pk.x, pk.y, pk.z, pk.w };
            float4* d4 = (float4*)(op + q * 16);
            #pragma unroll
            for (int j = 0; j < 4; j++) {
                float4 f;
                f.x = fminf((float)( ws[j]        & 255u), clampv) / clampv;
                f.y = fminf((float)((ws[j] >> 8 ) & 255u), clampv) / clampv;
                f.z = fminf((float)((ws[j] >> 16) & 255u), clampv) / clampv;
                f.w = fminf((float)((ws[j] >> 24) & 255u), clampv) / clampv;
                d4[j] = f;
            }
        }
        return;
    }

    const int* src = g_cont + (size_t)b * HW;
    if (t == 0) { s_sum = 0.0; s_sq = 0.0; }
    __syncthreads();
    double ls = 0.0, lq = 0.0;
    for (int p = t; p < HW; p += 512) {
        double v = (double)src[p];
        ls += v; lq += v * v;
    }
    for (int o = 16; o; o >>= 1) {
        ls += __shfl_down_sync(0xffffffffu, ls, o);
        lq += __shfl_down_sync(0xffffffffu, lq, o);
    }
    if ((t & 31) == 0) { atomicAdd(&s_sum, ls); atomicAdd(&s_sq, lq); }
    __syncthreads();
    double mu = s_sum / n;
    double var = (s_sq - s_sum * s_sum / n) / (n - 1.0);
    if (var < 0.0) var = 0.0;
    float clampv = (float)(mu + 3.0 * sqrt(var));
    float* op = out + (size_t)b * 2 * HW;
    for (int p = t; p < HW; p += 512) {
        float v = (float)src[p];
        op[p] = fminf(v, clampv) / clampv;
    }
}

// ---------------- launch ----------------
extern "C" void kernel_launch(void* const* d_in, const int* in_sizes, int n_in,
                              void* d_out, int out_size) {
    const int*   ev   = (const int*)d_in[0];
    const float* kern = (const float*)d_in[1];
    float*       out  = (float*)d_out;
    (void)in_sizes; (void)n_in; (void)out_size;

    k_hist<<<NB * NSEG, 256>>>(ev);
    k_mean<<<NB, 128>>>(kern);
    k_rowbits<<<NB * ROWS_USED, 256>>>();
    k_pref<<<NB * WBLK, 256>>>();
    k_decide<<<NB, 64>>>();
    k_conf<<<NB * WBLK, 256>>>();
    k_cont<<<NB * ROWS_USED, 256>>>();
    k_norm<<<NB * 2, 512>>>(out);
}